// round 14
// baseline (speedup 1.0000x reference)
#include <cuda_runtime.h>

#define NN 100000
#define EE 1600000
#define HH 64
#define TH 0.7f
#define ATT_EPS 1e-5f
#define SB1 512   // stage-1 blocks for stats

// ---------------- scratch (static device globals; no allocation) ----------------
__device__ float g_XW [NN*HH];
__device__ float g_Ya [NN*HH];
__device__ float g_Yb [NN*HH];
__device__ float g_Yc [NN*HH];
__device__ float g_S  [NN*HH];
__device__ float g_X2 [NN*HH];
__device__ float g_P  [NN*HH];
__device__ float g_T  [NN*HH];
__device__ float g_X3 [NN*HH];
__device__ float g_A  [NN*HH];
__device__ float g_ATT[NN*HH];
__device__ float g_VC [NN*HH];
__device__ float g_norm1[EE];
__device__ float g_norm2[EE];
__device__ int   g_cnt [NN];
__device__ int   g_cnt2[NN];
__device__ int   g_rowptr[NN+1];
__device__ int   g_cursor[NN];
__device__ int   g_eids[EE];
__device__ float g_dis1[NN];
__device__ float g_dis2[NN];
__device__ float g_self1[NN];
__device__ float g_self2[NN];
__device__ float g_stats[18*128];     // 18 BN slots x (sum[64], centered sumsq[64]) fp32
__device__ float g_part[SB1*64];      // stage-1 block partials

// reference rsqrt flavor: XLA CPU lowers lax.rsqrt to 1.0 / sqrt(x),
// i.e. correctly-rounded sqrt followed by correctly-rounded divide.
__device__ __forceinline__ float ref_rsqrt(float x) {
    return __fdiv_rn(1.0f, __fsqrt_rn(x));
}

// ---------------- small utility kernels ----------------
__global__ void k_setval(float* p, float v, int n) {
    int i = blockIdx.x*blockDim.x + threadIdx.x;
    if (i < n) p[i] = v;
}
__global__ void k_setvali(int* p, int v, int n) {
    int i = blockIdx.x*blockDim.x + threadIdx.x;
    if (i < n) p[i] = v;
}

// count in-edges (all + masked)
__global__ void k_count(const int* __restrict__ dst, const int* __restrict__ mask,
                        int* cnt, int* cnt2) {
    int e = blockIdx.x*blockDim.x + threadIdx.x;
    if (e >= EE) return;
    int d = dst[e];
    atomicAdd(&cnt[d], 1);
    if (mask[e]) atomicAdd(&cnt2[d], 1);
}

// single-block exclusive prefix sum over cnt -> rowptr, cursor
__global__ void k_scan(const int* __restrict__ cnt, int* rowptr, int* cursor) {
    __shared__ int sh[1024];
    __shared__ int carry;
    int tid = threadIdx.x;
    if (tid == 0) carry = 0;
    __syncthreads();
    for (int base = 0; base < NN; base += 1024) {
        int i = base + tid;
        int v = (i < NN) ? cnt[i] : 0;
        sh[tid] = v;
        __syncthreads();
        for (int off = 1; off < 1024; off <<= 1) {
            int t = (tid >= off) ? sh[tid-off] : 0;
            __syncthreads();
            sh[tid] += t;
            __syncthreads();
        }
        int excl = sh[tid] - v;
        if (i < NN) { rowptr[i] = carry + excl; cursor[i] = carry + excl; }
        __syncthreads();
        if (tid == 1023) carry += sh[1023];
        __syncthreads();
    }
    if (tid == 0) rowptr[NN] = carry;
}

__global__ void k_fill(const int* __restrict__ dst, int* cursor, int* eids) {
    int e = blockIdx.x*blockDim.x + threadIdx.x;
    if (e >= EE) return;
    int pos = atomicAdd(&cursor[dst[e]], 1);
    eids[pos] = e;
}

// per-node insertion sort so each bucket has edge ids ascending (stable order)
__global__ void k_sortbuckets(const int* __restrict__ rowptr, int* eids) {
    int n = blockIdx.x*blockDim.x + threadIdx.x;
    if (n >= NN) return;
    int beg = rowptr[n], end = rowptr[n+1];
    for (int i = beg+1; i < end; i++) {
        int key = eids[i];
        int j = i-1;
        while (j >= beg && eids[j] > key) { eids[j+1] = eids[j]; j--; }
        eids[j+1] = key;
    }
}

// dis = rsqrt(deg), selfw = dis*dis  (deg = 1 + count, exact integer)
__global__ void k_dis(const int* __restrict__ cnt, const int* __restrict__ cnt2,
                      float* dis1, float* dis2, float* s1, float* s2) {
    int i = blockIdx.x*blockDim.x + threadIdx.x;
    if (i >= NN) return;
    float d1 = (float)(cnt[i] + 1);
    float d2 = (float)(cnt2[i] + 1);
    float r1 = ref_rsqrt(d1), r2 = ref_rsqrt(d2);
    dis1[i] = r1; dis2[i] = r2;
    s1[i] = __fmul_rn(r1, r1);
    s2[i] = __fmul_rn(r2, r2);
}

// norm = (dis[src]*w)*dis[dst]  (replicating reference association)
__global__ void k_norm(const int* __restrict__ src, const int* __restrict__ dst,
                       const int* __restrict__ mask,
                       const float* __restrict__ dis1, const float* __restrict__ dis2,
                       float* norm1, float* norm2) {
    int e = blockIdx.x*blockDim.x + threadIdx.x;
    if (e >= EE) return;
    int s = src[e], d = dst[e];
    norm1[e] = __fmul_rn(dis1[s], dis1[d]);          // w1 = 1.0 exact
    float wf = mask[e] ? 1.0f : 0.0f;
    norm2[e] = __fmul_rn(__fmul_rn(dis2[s], wf), dis2[d]);
}

// ---------------- GEMM: XW = X @ W (k-ascending single-accumulator FMA) ----------------
__global__ void __launch_bounds__(256) k_gemm64(
    const float* __restrict__ X, const float* __restrict__ W,
    float* __restrict__ XW)
{
    __shared__ float Ws[64*64];
    __shared__ float xs[32*64];
    int tid = threadIdx.x;
    for (int i = tid; i < 64*64/4; i += 256)
        ((float4*)Ws)[i] = ((const float4*)W)[i];
    int rowBase = blockIdx.x * 32;
    const float4* Xg = (const float4*)(X + rowBase*64);
    for (int i = tid; i < 32*64/4; i += 256)
        ((float4*)xs)[i] = Xg[i];
    __syncthreads();

    int warp = tid >> 5, lane = tid & 31;
    int r0 = warp * 4;
    float acc[4][2] = {};
    #pragma unroll 8
    for (int k = 0; k < 64; k++) {
        float2 wv = *(const float2*)&Ws[k*64 + 2*lane];
        #pragma unroll
        for (int r = 0; r < 4; r++) {
            float xv = xs[(r0+r)*64 + k];
            acc[r][0] = __fmaf_rn(xv, wv.x, acc[r][0]);
            acc[r][1] = __fmaf_rn(xv, wv.y, acc[r][1]);
        }
    }
    #pragma unroll
    for (int r = 0; r < 4; r++) {
        int n = rowBase + r0 + r;
        *(float2*)&XW[n*64 + 2*lane] = make_float2(acc[r][0], acc[r][1]);
    }
}

// ---------------- gather: Y[n] = ((sum_{e asc} round(nrm*XW[src])) + selfw*XW[n]) + bias --
__global__ void __launch_bounds__(256) k_gather(
    const float* __restrict__ XW, const float* __restrict__ nrm,
    const int* __restrict__ srcarr,
    const int* __restrict__ eids, const int* __restrict__ rowptr,
    const float* __restrict__ selfw, const float* __restrict__ bias,
    float* __restrict__ Y)
{
    int w = blockIdx.x*8 + (threadIdx.x >> 5);     // 0 .. 2*NN-1
    int n = w >> 1, half = w & 1;
    int lane = threadIdx.x & 31;
    int col = half*32 + lane;
    int beg = rowptr[n], end = rowptr[n+1];
    float y = 0.0f;
    for (int p = beg; p < end; p++) {
        int e = eids[p];
        int s = srcarr[e];
        y = __fadd_rn(y, __fmul_rn(nrm[e], XW[s*64 + col]));
    }
    y = __fadd_rn(y, __fmul_rn(selfw[n], XW[n*64 + col]));
    y = __fadd_rn(y, bias[col]);
    Y[n*64 + col] = y;
}

// ================= stats: deterministic two-stage fp32 tree =================
__global__ void __launch_bounds__(256) k_stats_mean1(const float* __restrict__ Y, float* part)
{
    int tid = threadIdx.x;
    float s = 0.f;
    for (int i = blockIdx.x*256 + tid; i < NN*HH; i += SB1*256)
        s = __fadd_rn(s, Y[i]);
    __shared__ float ss[256];
    ss[tid] = s;
    __syncthreads();
    if (tid < 64) {
        float a = __fadd_rn(ss[tid],     ss[tid+64]);
        float b = __fadd_rn(ss[tid+128], ss[tid+192]);
        part[blockIdx.x*64 + tid] = __fadd_rn(a, b);
    }
}
__global__ void __launch_bounds__(256) k_stats_var1(const float* __restrict__ Y,
                                                    const float* __restrict__ st, float* part)
{
    __shared__ float m_sh[64];
    int tid = threadIdx.x;
    if (tid < 64) m_sh[tid] = __fdiv_rn(st[tid], 100000.0f);
    __syncthreads();
    int col = tid & 63;
    float m = m_sh[col];
    float q = 0.f;
    for (int i = blockIdx.x*256 + tid; i < NN*HH; i += SB1*256) {
        float d = __fsub_rn(Y[i], m);
        q = __fadd_rn(q, __fmul_rn(d, d));
    }
    __shared__ float sq[256];
    sq[tid] = q;
    __syncthreads();
    if (tid < 64) {
        float a = __fadd_rn(sq[tid],     sq[tid+64]);
        float b = __fadd_rn(sq[tid+128], sq[tid+192]);
        part[blockIdx.x*64 + tid] = __fadd_rn(a, b);
    }
}
__global__ void __launch_bounds__(256) k_stats_comb(const float* __restrict__ part, float* out)
{
    int col = blockIdx.x;          // 0..63
    int tid = threadIdx.x;         // 0..255
    __shared__ float sh[256];
    sh[tid] = __fadd_rn(part[tid*64 + col], part[(tid+256)*64 + col]);
    __syncthreads();
    for (int off = 128; off > 0; off >>= 1) {
        if (tid < off) sh[tid] = __fadd_rn(sh[tid], sh[tid+off]);
        __syncthreads();
    }
    if (tid == 0) out[col] = sh[0];
}

// coef = {mean_f, rstd_f, g, b}; apply is (((x-m)*rstd)*g)+b with _rn ops
__device__ __forceinline__ float4 bn_coef4(const float* st, const float* g,
                                           const float* b, int col) {
    float m   = __fdiv_rn(st[col],    100000.0f);
    float var = __fdiv_rn(st[64+col], 100000.0f);
    float rstd = ref_rsqrt(__fadd_rn(var, ATT_EPS));
    return make_float4(m, rstd, g[col], b[col]);
}

__device__ __forceinline__ float bn_apply(float x, float4 c) {
    return __fadd_rn(__fmul_rn(__fmul_rn(__fsub_rn(x, c.x), c.y), c.z), c.w);
}

// ---------------- BN apply + conv_lif (stateful) ----------------
__global__ void __launch_bounds__(256) k_apply_lif(
    const float* __restrict__ Y, const float* __restrict__ st,
    const float* __restrict__ g, const float* __restrict__ b,
    float* __restrict__ vc, float* __restrict__ S)
{
    __shared__ float4 c[64];
    if (threadIdx.x < 64) c[threadIdx.x] = bn_coef4(st, g, b, threadIdx.x);
    __syncthreads();
    int i = blockIdx.x*256 + threadIdx.x;
    int col = threadIdx.x & 63;
    float y = bn_apply(Y[i], c[col]);
    float v = __fadd_rn(vc[i], y);
    float s = (v >= TH) ? 1.0f : 0.0f;
    vc[i] = __fmul_rn(v, __fsub_rn(1.0f, s));
    S[i] = s;
}

// ---------------- BN apply, keep x2 + pos spike ----------------
__global__ void __launch_bounds__(256) k_apply_x2(
    const float* __restrict__ Y, const float* __restrict__ st,
    const float* __restrict__ g, const float* __restrict__ b,
    float* __restrict__ X2, float* __restrict__ P)
{
    __shared__ float4 c[64];
    if (threadIdx.x < 64) c[threadIdx.x] = bn_coef4(st, g, b, threadIdx.x);
    __syncthreads();
    int i = blockIdx.x*256 + threadIdx.x;
    int col = threadIdx.x & 63;
    float y = bn_apply(Y[i], c[col]);
    X2[i] = y;
    P[i] = (y >= TH) ? 1.0f : 0.0f;
}

// ---------------- t = alpha*bn(Y) + other ; store T ----------------
__global__ void __launch_bounds__(256) k_apply_mix(
    const float* __restrict__ Y, const float* __restrict__ st,
    const float* __restrict__ g, const float* __restrict__ b,
    const float* __restrict__ other, float alpha,
    float* __restrict__ T)
{
    __shared__ float4 c[64];
    if (threadIdx.x < 64) c[threadIdx.x] = bn_coef4(st, g, b, threadIdx.x);
    __syncthreads();
    int i = blockIdx.x*256 + threadIdx.x;
    int col = threadIdx.x & 63;
    float y = bn_apply(Y[i], c[col]);
    T[i] = __fadd_rn(__fmul_rn(alpha, y), other[i]);   // alpha=1 or 0.125 (exact mul)
}

// ---------------- bn(T) -> X3 ; conv_lif -> A (stateful) ----------------
__global__ void __launch_bounds__(256) k_apply_bnlif(
    const float* __restrict__ T, const float* __restrict__ st,
    const float* __restrict__ g, const float* __restrict__ b,
    float* __restrict__ vc, float* __restrict__ X3, float* __restrict__ A)
{
    __shared__ float4 c[64];
    if (threadIdx.x < 64) c[threadIdx.x] = bn_coef4(st, g, b, threadIdx.x);
    __syncthreads();
    int i = blockIdx.x*256 + threadIdx.x;
    int col = threadIdx.x & 63;
    float x3 = bn_apply(T[i], c[col]);
    X3[i] = x3;
    float v = __fadd_rn(vc[i], x3);
    float s = (v >= TH) ? 1.0f : 0.0f;
    vc[i] = __fmul_rn(v, __fsub_rn(1.0f, s));
    A[i] = s;
}

// ---------------- q,k,v spikes -> attention (warp per node) ----------------
__global__ void __launch_bounds__(256) k_apply_qkv(
    const float* __restrict__ Yq, const float* __restrict__ Yk, const float* __restrict__ Yv,
    const float* __restrict__ stq, const float* __restrict__ stk, const float* __restrict__ stv,
    const float* __restrict__ gq, const float* __restrict__ bq,
    const float* __restrict__ gk, const float* __restrict__ bk,
    const float* __restrict__ gv, const float* __restrict__ bv,
    float* __restrict__ ATT)
{
    __shared__ float4 cq[64], ck[64], cv[64];
    int t = threadIdx.x;
    if (t < 64)            cq[t]     = bn_coef4(stq, gq, bq, t);
    else if (t < 128)      ck[t-64]  = bn_coef4(stk, gk, bk, t-64);
    else if (t < 192)      cv[t-128] = bn_coef4(stv, gv, bv, t-128);
    __syncthreads();
    int node = blockIdx.x*8 + (t >> 5);
    int lane = t & 31;
    int i0 = node*64 + lane, i1 = i0 + 32;
    bool q0 = bn_apply(Yq[i0], cq[lane])    >= TH;
    bool q1 = bn_apply(Yq[i1], cq[lane+32]) >= TH;
    bool k0 = bn_apply(Yk[i0], ck[lane])    >= TH;
    bool k1 = bn_apply(Yk[i1], ck[lane+32]) >= TH;
    bool v0 = bn_apply(Yv[i0], cv[lane])    >= TH;
    bool v1 = bn_apply(Yv[i1], cv[lane+32]) >= TH;
    unsigned m0 = __ballot_sync(0xFFFFFFFFu, q0 && k0);
    unsigned m1 = __ballot_sync(0xFFFFFFFFu, q1 && k1);
    int cnt = __popc(m0) + __popc(m1);
    // qk mean = cnt/64 exact; spike(cnt/64 - 0.2) <=> cnt >= 13 (exact in fp32)
    float a = (cnt >= 13) ? 1.0f : 0.0f;
    ATT[i0] = a * (v0 ? 1.0f : 0.0f);
    ATT[i1] = a * (v1 ? 1.0f : 0.0f);
}

// ---------------- final: out = bn8(T); z = rowsum(out @ W_lin), replicated order --------
__global__ void __launch_bounds__(256) k_final(
    const float* __restrict__ T, const float* __restrict__ st,
    const float* __restrict__ g, const float* __restrict__ b,
    const float* __restrict__ Wl, float* __restrict__ z)
{
    __shared__ float4 c[64];
    __shared__ float Wls[64*64];
    int tid = threadIdx.x;
    if (tid < 64) c[tid] = bn_coef4(st, g, b, tid);
    for (int i = tid; i < 64*64/4; i += 256)
        ((float4*)Wls)[i] = ((const float4*)Wl)[i];
    __syncthreads();
    int n = blockIdx.x*256 + tid;
    if (n >= NN) return;
    float yv[64];
    #pragma unroll
    for (int k = 0; k < 64; k++)
        yv[k] = bn_apply(T[n*64 + k], c[k]);
    float zacc = 0.0f;
    for (int j = 0; j < 64; j++) {
        float p = 0.0f;
        #pragma unroll
        for (int k = 0; k < 64; k++)
            p = __fmaf_rn(yv[k], Wls[k*64 + j], p);
        zacc = __fadd_rn(zacc, p);
    }
    z[n] = zacc;
}

// ---------------- host orchestration ----------------
static void run_enc(const float* x, const float* Wg, const float* bg,
                    const float* bn_g, const float* bn_b,
                    const int* srcarr, const float* nrm, const float* selfw,
                    const int* eids, const int* rowptr,
                    float* stats_base, float* part, const float* Wl, float* zout,
                    float* XW, float* Ya, float* Yb, float* Yc,
                    float* S, float* X2, float* P, float* T, float* X3,
                    float* A, float* ATT, float* VC)
{
    const int GB = NN/32;        // 3125
    const int HB = (2*NN)/8;     // 25000 (warp per node-half)
    const int PB = NN*HH/256;    // 25000
    const int WB = NN/8;         // 12500
    const int FB = (NN+255)/256; // 391
    #define ST(i) (stats_base + (i)*128)
    #define STATS(buf, i) do { \
        k_stats_mean1<<<SB1,256>>>(buf, part); \
        k_stats_comb <<<64,256>>>(part, ST(i)); \
        k_stats_var1 <<<SB1,256>>>(buf, ST(i), part); \
        k_stats_comb <<<64,256>>>(part, ST(i)+64); } while (0)

    // 1: gcn(x, W0) -> bn0 -> conv_lif
    k_gemm64 <<<GB,256>>>(x, Wg+0*4096, XW);
    k_gather <<<HB,256>>>(XW, nrm, srcarr, eids, rowptr, selfw, bg+0*64, Ya);
    STATS(Ya, 0);
    k_apply_lif<<<PB,256>>>(Ya, ST(0), bn_g+0*64, bn_b+0*64, VC, S);
    // 2: gcn(S, W1) -> bn1 -> keep x2, pos spike P
    k_gemm64 <<<GB,256>>>(S, Wg+1*4096, XW);
    k_gather <<<HB,256>>>(XW, nrm, srcarr, eids, rowptr, selfw, bg+1*64, Ya);
    STATS(Ya, 1);
    k_apply_x2<<<PB,256>>>(Ya, ST(1), bn_g+1*64, bn_b+1*64, X2, P);
    // 3: gcn(P, W2) -> bn2 ; t = bn2 + x2 ; stats(t) into slot 3
    k_gemm64 <<<GB,256>>>(P, Wg+2*4096, XW);
    k_gather <<<HB,256>>>(XW, nrm, srcarr, eids, rowptr, selfw, bg+2*64, Ya);
    STATS(Ya, 2);
    k_apply_mix<<<PB,256>>>(Ya, ST(2), bn_g+2*64, bn_b+2*64, X2, 1.0f, T);
    STATS(T, 3);
    // bn3 -> X3 ; conv_lif -> A
    k_apply_bnlif<<<PB,256>>>(T, ST(3), bn_g+3*64, bn_b+3*64, VC, X3, A);
    // q,k,v GCNs from A
    k_gemm64 <<<GB,256>>>(A, Wg+3*4096, XW);
    k_gather <<<HB,256>>>(XW, nrm, srcarr, eids, rowptr, selfw, bg+3*64, Ya);
    STATS(Ya, 4);
    k_gemm64 <<<GB,256>>>(A, Wg+4*4096, XW);
    k_gather <<<HB,256>>>(XW, nrm, srcarr, eids, rowptr, selfw, bg+4*64, Yb);
    STATS(Yb, 5);
    k_gemm64 <<<GB,256>>>(A, Wg+5*4096, XW);
    k_gather <<<HB,256>>>(XW, nrm, srcarr, eids, rowptr, selfw, bg+5*64, Yc);
    STATS(Yc, 6);
    k_apply_qkv<<<WB,256>>>(Ya, Yb, Yc, ST(4), ST(5), ST(6),
                            bn_g+4*64, bn_b+4*64, bn_g+5*64, bn_b+5*64,
                            bn_g+6*64, bn_b+6*64, ATT);
    // att gcn -> bn7 ; t2 = x3 + 0.125*bn7 ; stats(t2) into slot 8
    k_gemm64 <<<GB,256>>>(ATT, Wg+6*4096, XW);
    k_gather <<<HB,256>>>(XW, nrm, srcarr, eids, rowptr, selfw, bg+6*64, Ya);
    STATS(Ya, 7);
    k_apply_mix<<<PB,256>>>(Ya, ST(7), bn_g+7*64, bn_b+7*64, X3, 0.125f, T);
    STATS(T, 8);
    // final bn8 + decode
    k_final<<<FB,256>>>(T, ST(8), bn_g+8*64, bn_b+8*64, Wl, zout);
    #undef STATS
    #undef ST
}

extern "C" void kernel_launch(void* const* d_in, const int* in_sizes, int n_in,
                              void* d_out, int out_size)
{
    const float* x    = (const float*)d_in[0];
    const int*   ei   = (const int*)  d_in[1];
    const int*   src  = ei;
    const int*   dst  = ei + EE;
    const int*   mask = (const int*)  d_in[2];
    const float* Wg   = (const float*)d_in[3];
    const float* bg   = (const float*)d_in[4];
    const float* bn_g = (const float*)d_in[5];
    const float* bn_b = (const float*)d_in[6];
    const float* Wl   = (const float*)d_in[7];
    float* z = (float*)d_out;

    float *XW,*Ya,*Yb,*Yc,*S,*X2,*P,*T,*X3,*A,*ATT,*VC;
    float *n1,*n2,*ds1,*ds2,*sf1,*sf2,*stats,*part;
    int *cnt,*cnt2,*rowptr,*cursor,*eids;
    cudaGetSymbolAddress((void**)&XW,  g_XW);
    cudaGetSymbolAddress((void**)&Ya,  g_Ya);
    cudaGetSymbolAddress((void**)&Yb,  g_Yb);
    cudaGetSymbolAddress((void**)&Yc,  g_Yc);
    cudaGetSymbolAddress((void**)&S,   g_S);
    cudaGetSymbolAddress((void**)&X2,  g_X2);
    cudaGetSymbolAddress((void**)&P,   g_P);
    cudaGetSymbolAddress((void**)&T,   g_T);
    cudaGetSymbolAddress((void**)&X3,  g_X3);
    cudaGetSymbolAddress((void**)&A,   g_A);
    cudaGetSymbolAddress((void**)&ATT, g_ATT);
    cudaGetSymbolAddress((void**)&VC,  g_VC);
    cudaGetSymbolAddress((void**)&n1,  g_norm1);
    cudaGetSymbolAddress((void**)&n2,  g_norm2);
    cudaGetSymbolAddress((void**)&cnt, g_cnt);
    cudaGetSymbolAddress((void**)&cnt2,g_cnt2);
    cudaGetSymbolAddress((void**)&rowptr, g_rowptr);
    cudaGetSymbolAddress((void**)&cursor, g_cursor);
    cudaGetSymbolAddress((void**)&eids,   g_eids);
    cudaGetSymbolAddress((void**)&ds1, g_dis1);
    cudaGetSymbolAddress((void**)&ds2, g_dis2);
    cudaGetSymbolAddress((void**)&sf1, g_self1);
    cudaGetSymbolAddress((void**)&sf2, g_self2);
    cudaGetSymbolAddress((void**)&stats, g_stats);
    cudaGetSymbolAddress((void**)&part,  g_part);

    // ---- per-launch init (graph replays everything; state reset in-graph) ----
    k_setvali<<<(NN+255)/256,256>>>(cnt,  0, NN);
    k_setvali<<<(NN+255)/256,256>>>(cnt2, 0, NN);
    k_setval <<<(NN*HH+255)/256,256>>>(VC, 0.0f, NN*HH);
    k_count<<<(EE+255)/256,256>>>(dst, mask, cnt, cnt2);
    k_scan <<<1,1024>>>(cnt, rowptr, cursor);
    k_fill <<<(EE+255)/256,256>>>(dst, cursor, eids);
    k_sortbuckets<<<(NN+255)/256,256>>>(rowptr, eids);
    k_dis  <<<(NN+255)/256,256>>>(cnt, cnt2, ds1, ds2, sf1, sf2);
    k_norm <<<(EE+255)/256,256>>>(src, dst, mask, ds1, ds2, n1, n2);

    // enc 1 (w = ones), enc 2 (w = mask); conv_lif state VC carries over
    run_enc(x, Wg, bg, bn_g, bn_b, src, n1, sf1, eids, rowptr,
            stats,        part, Wl, z,
            XW, Ya, Yb, Yc, S, X2, P, T, X3, A, ATT, VC);
    run_enc(x, Wg, bg, bn_g, bn_b, src, n2, sf2, eids, rowptr,
            stats+9*128,  part, Wl, z+NN,
            XW, Ya, Yb, Yc, S, X2, P, T, X3, A, ATT, VC);
}

// round 15
// speedup vs baseline: 1.4733x; 1.4733x over previous
#include <cuda_runtime.h>

#define NN 100000
#define EE 1600000
#define HH 64
#define TH 0.7f
#define ATT_EPS 1e-5f
#define SB1 512   // stage-1 blocks for stats
#define NB 98     // scan blocks of 1024

// ---------------- scratch (static device globals; no allocation) ----------------
__device__ float g_XW [NN*HH];
__device__ float g_XWb[NN*HH];
__device__ float g_XWc[NN*HH];
__device__ float g_Ya [NN*HH];
__device__ float g_Yb [NN*HH];
__device__ float g_Yc [NN*HH];
__device__ float g_S  [NN*HH];
__device__ float g_X2 [NN*HH];
__device__ float g_P  [NN*HH];
__device__ float g_T  [NN*HH];
__device__ float g_X3 [NN*HH];
__device__ float g_A  [NN*HH];
__device__ float g_ATT[NN*HH];
__device__ float g_VC [NN*HH];
__device__ int   g_cnt [NN];
__device__ int   g_cnt2[NN];
__device__ int   g_rowptr[NN+1];
__device__ int   g_cursor[NN];
__device__ int   g_eids[EE];
__device__ int   g_srcP[EE];
__device__ float g_nrmP1[EE];
__device__ float g_nrmP2[EE];
__device__ int   g_bsum[NB];
__device__ int   g_boff[NB];
__device__ float g_dis1[NN];
__device__ float g_dis2[NN];
__device__ float g_self1[NN];
__device__ float g_self2[NN];
__device__ float g_stats[18*128];     // 18 BN slots x (sum[64], centered sumsq[64]) fp32
__device__ float g_part[SB1*64];      // stage-1 block partials

// reference rsqrt flavor: XLA lowers lax.rsqrt to 1.0 / sqrt(x)
__device__ __forceinline__ float ref_rsqrt(float x) {
    return __fdiv_rn(1.0f, __fsqrt_rn(x));
}

// ---------------- init: zero cnt, cnt2, VC in one kernel ----------------
__global__ void k_init(int* cnt, int* cnt2, float* vc) {
    for (int i = blockIdx.x*blockDim.x + threadIdx.x; i < NN*HH; i += gridDim.x*blockDim.x) {
        vc[i] = 0.0f;
        if (i < NN) { cnt[i] = 0; cnt2[i] = 0; }
    }
}

// count in-edges (all + masked)
__global__ void k_count(const int* __restrict__ dst, const int* __restrict__ mask,
                        int* cnt, int* cnt2) {
    int e = blockIdx.x*blockDim.x + threadIdx.x;
    if (e >= EE) return;
    int d = dst[e];
    atomicAdd(&cnt[d], 1);
    if (mask[e]) atomicAdd(&cnt2[d], 1);
}

// ---------------- 3-kernel exclusive scan over cnt -> rowptr ----------------
__global__ void k_scan1(const int* __restrict__ cnt, int* rowptr, int* bsum) {
    __shared__ int sh[1024];
    int tid = threadIdx.x;
    int i = blockIdx.x*1024 + tid;
    int v = (i < NN) ? cnt[i] : 0;
    sh[tid] = v;
    __syncthreads();
    for (int off = 1; off < 1024; off <<= 1) {
        int t = (tid >= off) ? sh[tid-off] : 0;
        __syncthreads();
        sh[tid] += t;
        __syncthreads();
    }
    if (i < NN) rowptr[i] = sh[tid] - v;   // block-local exclusive
    if (tid == 1023) bsum[blockIdx.x] = sh[1023];
}
__global__ void k_scan2(const int* __restrict__ bsum, int* boff, int* rowptr) {
    // single block, sequential exact integer scan of NB totals
    if (threadIdx.x == 0) {
        int acc = 0;
        for (int b = 0; b < NB; b++) { boff[b] = acc; acc += bsum[b]; }
        rowptr[NN] = acc;
    }
}
__global__ void k_scan3(const int* __restrict__ boff, int* rowptr, int* cursor) {
    int i = blockIdx.x*blockDim.x + threadIdx.x;
    if (i >= NN) return;
    int r = rowptr[i] + boff[i >> 10];
    rowptr[i] = r;
    cursor[i] = r;
}

__global__ void k_fill(const int* __restrict__ dst, int* cursor, int* eids) {
    int e = blockIdx.x*blockDim.x + threadIdx.x;
    if (e >= EE) return;
    int pos = atomicAdd(&cursor[dst[e]], 1);
    eids[pos] = e;
}

// per-node insertion sort so each bucket has edge ids ascending (stable order)
__global__ void k_sortbuckets(const int* __restrict__ rowptr, int* eids) {
    int n = blockIdx.x*blockDim.x + threadIdx.x;
    if (n >= NN) return;
    int beg = rowptr[n], end = rowptr[n+1];
    for (int i = beg+1; i < end; i++) {
        int key = eids[i];
        int j = i-1;
        while (j >= beg && eids[j] > key) { eids[j+1] = eids[j]; j--; }
        eids[j+1] = key;
    }
}

// dis = rsqrt(deg), selfw = dis*dis  (deg = 1 + count, exact integer)
__global__ void k_dis(const int* __restrict__ cnt, const int* __restrict__ cnt2,
                      float* dis1, float* dis2, float* s1, float* s2) {
    int i = blockIdx.x*blockDim.x + threadIdx.x;
    if (i >= NN) return;
    float d1 = (float)(cnt[i] + 1);
    float d2 = (float)(cnt2[i] + 1);
    float r1 = ref_rsqrt(d1), r2 = ref_rsqrt(d2);
    dis1[i] = r1; dis2[i] = r2;
    s1[i] = __fmul_rn(r1, r1);
    s2[i] = __fmul_rn(r2, r2);
}

// permute metadata into CSR order: srcP[p], nrmP1[p], nrmP2[p]
// same float formulas as before -> identical bits per edge
__global__ void k_permute(const int* __restrict__ eids,
                          const int* __restrict__ src, const int* __restrict__ dst,
                          const int* __restrict__ mask,
                          const float* __restrict__ dis1, const float* __restrict__ dis2,
                          int* srcP, float* nrmP1, float* nrmP2) {
    int p = blockIdx.x*blockDim.x + threadIdx.x;
    if (p >= EE) return;
    int e = eids[p];
    int s = src[e], d = dst[e];
    srcP[p] = s;
    nrmP1[p] = __fmul_rn(dis1[s], dis1[d]);          // w1 = 1.0 exact
    float wf = mask[e] ? 1.0f : 0.0f;
    nrmP2[p] = __fmul_rn(__fmul_rn(dis2[s], wf), dis2[d]);
}

// ---------------- GEMM: XW = X @ W (k-ascending single-accumulator FMA) ----------------
__global__ void __launch_bounds__(256) k_gemm64(
    const float* __restrict__ X, const float* __restrict__ W,
    float* __restrict__ XW)
{
    __shared__ float Ws[64*64];
    __shared__ float xs[32*64];
    int tid = threadIdx.x;
    for (int i = tid; i < 64*64/4; i += 256)
        ((float4*)Ws)[i] = ((const float4*)W)[i];
    int rowBase = blockIdx.x * 32;
    const float4* Xg = (const float4*)(X + rowBase*64);
    for (int i = tid; i < 32*64/4; i += 256)
        ((float4*)xs)[i] = Xg[i];
    __syncthreads();

    int warp = tid >> 5, lane = tid & 31;
    int r0 = warp * 4;
    float acc[4][2] = {};
    #pragma unroll 8
    for (int k = 0; k < 64; k++) {
        float2 wv = *(const float2*)&Ws[k*64 + 2*lane];
        #pragma unroll
        for (int r = 0; r < 4; r++) {
            float xv = xs[(r0+r)*64 + k];
            acc[r][0] = __fmaf_rn(xv, wv.x, acc[r][0]);
            acc[r][1] = __fmaf_rn(xv, wv.y, acc[r][1]);
        }
    }
    #pragma unroll
    for (int r = 0; r < 4; r++) {
        int n = rowBase + r0 + r;
        *(float2*)&XW[n*64 + 2*lane] = make_float2(acc[r][0], acc[r][1]);
    }
}

// ---------------- gather (warp per node, float2 cols, batched metadata) ----------------
// per column: y = ((sum_{p asc} round(nrmP[p]*XW[srcP[p],col])) + selfw*XW[n,col]) + bias
__global__ void __launch_bounds__(256) k_gather(
    const float* __restrict__ XW, const float* __restrict__ nrmP,
    const int* __restrict__ srcP, const int* __restrict__ rowptr,
    const float* __restrict__ selfw, const float* __restrict__ bias,
    float* __restrict__ Y)
{
    int n = blockIdx.x*8 + (threadIdx.x >> 5);
    int lane = threadIdx.x & 31;
    const float2* XW2 = (const float2*)XW;
    int beg = rowptr[n], end = rowptr[n+1];
    float y0 = 0.0f, y1 = 0.0f;
    for (int chunk = beg; chunk < end; chunk += 32) {
        int m = end - chunk; if (m > 32) m = 32;
        int   sf = (lane < m) ? srcP[chunk+lane] : 0;
        float wf = (lane < m) ? nrmP[chunk+lane] : 0.0f;
        for (int j = 0; j < m; j++) {
            int   s = __shfl_sync(0xFFFFFFFFu, sf, j);
            float w = __shfl_sync(0xFFFFFFFFu, wf, j);
            float2 v = XW2[s*32 + lane];
            y0 = __fadd_rn(y0, __fmul_rn(w, v.x));
            y1 = __fadd_rn(y1, __fmul_rn(w, v.y));
        }
    }
    float sw = selfw[n];
    float2 vs = XW2[n*32 + lane];
    y0 = __fadd_rn(y0, __fmul_rn(sw, vs.x));
    y1 = __fadd_rn(y1, __fmul_rn(sw, vs.y));
    y0 = __fadd_rn(y0, bias[2*lane]);
    y1 = __fadd_rn(y1, bias[2*lane+1]);
    ((float2*)Y)[n*32 + lane] = make_float2(y0, y1);
}

// fused q,k,v gather: one metadata pass, three XW buffers
__global__ void __launch_bounds__(256) k_gather3(
    const float* __restrict__ XWa, const float* __restrict__ XWb, const float* __restrict__ XWc,
    const float* __restrict__ nrmP, const int* __restrict__ srcP,
    const int* __restrict__ rowptr, const float* __restrict__ selfw,
    const float* __restrict__ ba, const float* __restrict__ bb, const float* __restrict__ bc,
    float* __restrict__ Ya, float* __restrict__ Yb, float* __restrict__ Yc)
{
    int n = blockIdx.x*8 + (threadIdx.x >> 5);
    int lane = threadIdx.x & 31;
    const float2* A2 = (const float2*)XWa;
    const float2* B2 = (const float2*)XWb;
    const float2* C2 = (const float2*)XWc;
    int beg = rowptr[n], end = rowptr[n+1];
    float a0=0.f,a1=0.f,b0=0.f,b1=0.f,c0=0.f,c1=0.f;
    for (int chunk = beg; chunk < end; chunk += 32) {
        int m = end - chunk; if (m > 32) m = 32;
        int   sf = (lane < m) ? srcP[chunk+lane] : 0;
        float wf = (lane < m) ? nrmP[chunk+lane] : 0.0f;
        for (int j = 0; j < m; j++) {
            int   s = __shfl_sync(0xFFFFFFFFu, sf, j);
            float w = __shfl_sync(0xFFFFFFFFu, wf, j);
            float2 va = A2[s*32 + lane];
            float2 vb = B2[s*32 + lane];
            float2 vc = C2[s*32 + lane];
            a0 = __fadd_rn(a0, __fmul_rn(w, va.x));
            a1 = __fadd_rn(a1, __fmul_rn(w, va.y));
            b0 = __fadd_rn(b0, __fmul_rn(w, vb.x));
            b1 = __fadd_rn(b1, __fmul_rn(w, vb.y));
            c0 = __fadd_rn(c0, __fmul_rn(w, vc.x));
            c1 = __fadd_rn(c1, __fmul_rn(w, vc.y));
        }
    }
    float sw = selfw[n];
    float2 va = A2[n*32 + lane], vb = B2[n*32 + lane], vc = C2[n*32 + lane];
    a0 = __fadd_rn(a0, __fmul_rn(sw, va.x)); a1 = __fadd_rn(a1, __fmul_rn(sw, va.y));
    b0 = __fadd_rn(b0, __fmul_rn(sw, vb.x)); b1 = __fadd_rn(b1, __fmul_rn(sw, vb.y));
    c0 = __fadd_rn(c0, __fmul_rn(sw, vc.x)); c1 = __fadd_rn(c1, __fmul_rn(sw, vc.y));
    a0 = __fadd_rn(a0, ba[2*lane]); a1 = __fadd_rn(a1, ba[2*lane+1]);
    b0 = __fadd_rn(b0, bb[2*lane]); b1 = __fadd_rn(b1, bb[2*lane+1]);
    c0 = __fadd_rn(c0, bc[2*lane]); c1 = __fadd_rn(c1, bc[2*lane+1]);
    ((float2*)Ya)[n*32 + lane] = make_float2(a0, a1);
    ((float2*)Yb)[n*32 + lane] = make_float2(b0, b1);
    ((float2*)Yc)[n*32 + lane] = make_float2(c0, c1);
}

// ================= stats: deterministic two-stage fp32 tree (unchanged bits) =============
__global__ void __launch_bounds__(256) k_stats_mean1(const float* __restrict__ Y, float* part)
{
    int tid = threadIdx.x;
    float s = 0.f;
    for (int i = blockIdx.x*256 + tid; i < NN*HH; i += SB1*256)
        s = __fadd_rn(s, Y[i]);
    __shared__ float ss[256];
    ss[tid] = s;
    __syncthreads();
    if (tid < 64) {
        float a = __fadd_rn(ss[tid],     ss[tid+64]);
        float b = __fadd_rn(ss[tid+128], ss[tid+192]);
        part[blockIdx.x*64 + tid] = __fadd_rn(a, b);
    }
}
__global__ void __launch_bounds__(256) k_stats_var1(const float* __restrict__ Y,
                                                    const float* __restrict__ st, float* part)
{
    __shared__ float m_sh[64];
    int tid = threadIdx.x;
    if (tid < 64) m_sh[tid] = __fdiv_rn(st[tid], 100000.0f);
    __syncthreads();
    int col = tid & 63;
    float m = m_sh[col];
    float q = 0.f;
    for (int i = blockIdx.x*256 + tid; i < NN*HH; i += SB1*256) {
        float d = __fsub_rn(Y[i], m);
        q = __fadd_rn(q, __fmul_rn(d, d));
    }
    __shared__ float sq[256];
    sq[tid] = q;
    __syncthreads();
    if (tid < 64) {
        float a = __fadd_rn(sq[tid],     sq[tid+64]);
        float b = __fadd_rn(sq[tid+128], sq[tid+192]);
        part[blockIdx.x*64 + tid] = __fadd_rn(a, b);
    }
}
__global__ void __launch_bounds__(256) k_stats_comb(const float* __restrict__ part, float* out)
{
    int col = blockIdx.x;          // 0..63
    int tid = threadIdx.x;         // 0..255
    __shared__ float sh[256];
    sh[tid] = __fadd_rn(part[tid*64 + col], part[(tid+256)*64 + col]);
    __syncthreads();
    for (int off = 128; off > 0; off >>= 1) {
        if (tid < off) sh[tid] = __fadd_rn(sh[tid], sh[tid+off]);
        __syncthreads();
    }
    if (tid == 0) out[col] = sh[0];
}

// coef = {mean_f, rstd_f, g, b}; apply is (((x-m)*rstd)*g)+b with _rn ops
__device__ __forceinline__ float4 bn_coef4(const float* st, const float* g,
                                           const float* b, int col) {
    float m   = __fdiv_rn(st[col],    100000.0f);
    float var = __fdiv_rn(st[64+col], 100000.0f);
    float rstd = ref_rsqrt(__fadd_rn(var, ATT_EPS));
    return make_float4(m, rstd, g[col], b[col]);
}

__device__ __forceinline__ float bn_apply(float x, float4 c) {
    return __fadd_rn(__fmul_rn(__fmul_rn(__fsub_rn(x, c.x), c.y), c.z), c.w);
}

// ---------------- BN apply + conv_lif (stateful) ----------------
__global__ void __launch_bounds__(256) k_apply_lif(
    const float* __restrict__ Y, const float* __restrict__ st,
    const float* __restrict__ g, const float* __restrict__ b,
    float* __restrict__ vc, float* __restrict__ S)
{
    __shared__ float4 c[64];
    if (threadIdx.x < 64) c[threadIdx.x] = bn_coef4(st, g, b, threadIdx.x);
    __syncthreads();
    int i = blockIdx.x*256 + threadIdx.x;
    int col = threadIdx.x & 63;
    float y = bn_apply(Y[i], c[col]);
    float v = __fadd_rn(vc[i], y);
    float s = (v >= TH) ? 1.0f : 0.0f;
    vc[i] = __fmul_rn(v, __fsub_rn(1.0f, s));
    S[i] = s;
}

// ---------------- BN apply, keep x2 + pos spike ----------------
__global__ void __launch_bounds__(256) k_apply_x2(
    const float* __restrict__ Y, const float* __restrict__ st,
    const float* __restrict__ g, const float* __restrict__ b,
    float* __restrict__ X2, float* __restrict__ P)
{
    __shared__ float4 c[64];
    if (threadIdx.x < 64) c[threadIdx.x] = bn_coef4(st, g, b, threadIdx.x);
    __syncthreads();
    int i = blockIdx.x*256 + threadIdx.x;
    int col = threadIdx.x & 63;
    float y = bn_apply(Y[i], c[col]);
    X2[i] = y;
    P[i] = (y >= TH) ? 1.0f : 0.0f;
}

// ---------------- t = alpha*bn(Y) + other ; store T ----------------
__global__ void __launch_bounds__(256) k_apply_mix(
    const float* __restrict__ Y, const float* __restrict__ st,
    const float* __restrict__ g, const float* __restrict__ b,
    const float* __restrict__ other, float alpha,
    float* __restrict__ T)
{
    __shared__ float4 c[64];
    if (threadIdx.x < 64) c[threadIdx.x] = bn_coef4(st, g, b, threadIdx.x);
    __syncthreads();
    int i = blockIdx.x*256 + threadIdx.x;
    int col = threadIdx.x & 63;
    float y = bn_apply(Y[i], c[col]);
    T[i] = __fadd_rn(__fmul_rn(alpha, y), other[i]);   // alpha=1 or 0.125 (exact mul)
}

// ---------------- bn(T) -> X3 ; conv_lif -> A (stateful) ----------------
__global__ void __launch_bounds__(256) k_apply_bnlif(
    const float* __restrict__ T, const float* __restrict__ st,
    const float* __restrict__ g, const float* __restrict__ b,
    float* __restrict__ vc, float* __restrict__ X3, float* __restrict__ A)
{
    __shared__ float4 c[64];
    if (threadIdx.x < 64) c[threadIdx.x] = bn_coef4(st, g, b, threadIdx.x);
    __syncthreads();
    int i = blockIdx.x*256 + threadIdx.x;
    int col = threadIdx.x & 63;
    float x3 = bn_apply(T[i], c[col]);
    X3[i] = x3;
    float v = __fadd_rn(vc[i], x3);
    float s = (v >= TH) ? 1.0f : 0.0f;
    vc[i] = __fmul_rn(v, __fsub_rn(1.0f, s));
    A[i] = s;
}

// ---------------- q,k,v spikes -> attention (warp per node) ----------------
__global__ void __launch_bounds__(256) k_apply_qkv(
    const float* __restrict__ Yq, const float* __restrict__ Yk, const float* __restrict__ Yv,
    const float* __restrict__ stq, const float* __restrict__ stk, const float* __restrict__ stv,
    const float* __restrict__ gq, const float* __restrict__ bq,
    const float* __restrict__ gk, const float* __restrict__ bk,
    const float* __restrict__ gv, const float* __restrict__ bv,
    float* __restrict__ ATT)
{
    __shared__ float4 cq[64], ck[64], cv[64];
    int t = threadIdx.x;
    if (t < 64)            cq[t]     = bn_coef4(stq, gq, bq, t);
    else if (t < 128)      ck[t-64]  = bn_coef4(stk, gk, bk, t-64);
    else if (t < 192)      cv[t-128] = bn_coef4(stv, gv, bv, t-128);
    __syncthreads();
    int node = blockIdx.x*8 + (t >> 5);
    int lane = t & 31;
    int i0 = node*64 + lane, i1 = i0 + 32;
    bool q0 = bn_apply(Yq[i0], cq[lane])    >= TH;
    bool q1 = bn_apply(Yq[i1], cq[lane+32]) >= TH;
    bool k0 = bn_apply(Yk[i0], ck[lane])    >= TH;
    bool k1 = bn_apply(Yk[i1], ck[lane+32]) >= TH;
    bool v0 = bn_apply(Yv[i0], cv[lane])    >= TH;
    bool v1 = bn_apply(Yv[i1], cv[lane+32]) >= TH;
    unsigned m0 = __ballot_sync(0xFFFFFFFFu, q0 && k0);
    unsigned m1 = __ballot_sync(0xFFFFFFFFu, q1 && k1);
    int cnt = __popc(m0) + __popc(m1);
    float a = (cnt >= 13) ? 1.0f : 0.0f;
    ATT[i0] = a * (v0 ? 1.0f : 0.0f);
    ATT[i1] = a * (v1 ? 1.0f : 0.0f);
}

// ---------------- final: out = bn8(T); z = rowsum(out @ W_lin), replicated order --------
__global__ void __launch_bounds__(256) k_final(
    const float* __restrict__ T, const float* __restrict__ st,
    const float* __restrict__ g, const float* __restrict__ b,
    const float* __restrict__ Wl, float* __restrict__ z)
{
    __shared__ float4 c[64];
    __shared__ float Wls[64*64];
    int tid = threadIdx.x;
    if (tid < 64) c[tid] = bn_coef4(st, g, b, tid);
    for (int i = tid; i < 64*64/4; i += 256)
        ((float4*)Wls)[i] = ((const float4*)Wl)[i];
    __syncthreads();
    int n = blockIdx.x*256 + tid;
    if (n >= NN) return;
    float yv[64];
    #pragma unroll
    for (int k = 0; k < 64; k++)
        yv[k] = bn_apply(T[n*64 + k], c[k]);
    float zacc = 0.0f;
    for (int j = 0; j < 64; j++) {
        float p = 0.0f;
        #pragma unroll
        for (int k = 0; k < 64; k++)
            p = __fmaf_rn(yv[k], Wls[k*64 + j], p);
        zacc = __fadd_rn(zacc, p);
    }
    z[n] = zacc;
}

// ---------------- host orchestration ----------------
static void run_enc(const float* x, const float* Wg, const float* bg,
                    const float* bn_g, const float* bn_b,
                    const float* nrmP, const int* srcP, const float* selfw,
                    const int* rowptr,
                    float* stats_base, float* part, const float* Wl, float* zout,
                    float* XW, float* XWb, float* XWc, float* Ya, float* Yb, float* Yc,
                    float* S, float* X2, float* P, float* T, float* X3,
                    float* A, float* ATT, float* VC)
{
    const int GB = NN/32;        // 3125
    const int WB = NN/8;         // 12500 (warp per node)
    const int PB = NN*HH/256;    // 25000
    const int FB = (NN+255)/256; // 391
    #define ST(i) (stats_base + (i)*128)
    #define STATS(buf, i) do { \
        k_stats_mean1<<<SB1,256>>>(buf, part); \
        k_stats_comb <<<64,256>>>(part, ST(i)); \
        k_stats_var1 <<<SB1,256>>>(buf, ST(i), part); \
        k_stats_comb <<<64,256>>>(part, ST(i)+64); } while (0)

    // 1: gcn(x, W0) -> bn0 -> conv_lif
    k_gemm64 <<<GB,256>>>(x, Wg+0*4096, XW);
    k_gather <<<WB,256>>>(XW, nrmP, srcP, rowptr, selfw, bg+0*64, Ya);
    STATS(Ya, 0);
    k_apply_lif<<<PB,256>>>(Ya, ST(0), bn_g+0*64, bn_b+0*64, VC, S);
    // 2: gcn(S, W1) -> bn1 -> keep x2, pos spike P
    k_gemm64 <<<GB,256>>>(S, Wg+1*4096, XW);
    k_gather <<<WB,256>>>(XW, nrmP, srcP, rowptr, selfw, bg+1*64, Ya);
    STATS(Ya, 1);
    k_apply_x2<<<PB,256>>>(Ya, ST(1), bn_g+1*64, bn_b+1*64, X2, P);
    // 3: gcn(P, W2) -> bn2 ; t = bn2 + x2 ; stats(t) into slot 3
    k_gemm64 <<<GB,256>>>(P, Wg+2*4096, XW);
    k_gather <<<WB,256>>>(XW, nrmP, srcP, rowptr, selfw, bg+2*64, Ya);
    STATS(Ya, 2);
    k_apply_mix<<<PB,256>>>(Ya, ST(2), bn_g+2*64, bn_b+2*64, X2, 1.0f, T);
    STATS(T, 3);
    // bn3 -> X3 ; conv_lif -> A
    k_apply_bnlif<<<PB,256>>>(T, ST(3), bn_g+3*64, bn_b+3*64, VC, X3, A);
    // q,k,v GCNs from A (3 gemms, one fused gather)
    k_gemm64 <<<GB,256>>>(A, Wg+3*4096, XW);
    k_gemm64 <<<GB,256>>>(A, Wg+4*4096, XWb);
    k_gemm64 <<<GB,256>>>(A, Wg+5*4096, XWc);
    k_gather3<<<WB,256>>>(XW, XWb, XWc, nrmP, srcP, rowptr, selfw,
                          bg+3*64, bg+4*64, bg+5*64, Ya, Yb, Yc);
    STATS(Ya, 4);
    STATS(Yb, 5);
    STATS(Yc, 6);
    k_apply_qkv<<<WB,256>>>(Ya, Yb, Yc, ST(4), ST(5), ST(6),
                            bn_g+4*64, bn_b+4*64, bn_g+5*64, bn_b+5*64,
                            bn_g+6*64, bn_b+6*64, ATT);
    // att gcn -> bn7 ; t2 = x3 + 0.125*bn7 ; stats(t2) into slot 8
    k_gemm64 <<<GB,256>>>(ATT, Wg+6*4096, XW);
    k_gather <<<WB,256>>>(XW, nrmP, srcP, rowptr, selfw, bg+6*64, Ya);
    STATS(Ya, 7);
    k_apply_mix<<<PB,256>>>(Ya, ST(7), bn_g+7*64, bn_b+7*64, X3, 0.125f, T);
    STATS(T, 8);
    // final bn8 + decode
    k_final<<<FB,256>>>(T, ST(8), bn_g+8*64, bn_b+8*64, Wl, zout);
    #undef STATS
    #undef ST
}

extern "C" void kernel_launch(void* const* d_in, const int* in_sizes, int n_in,
                              void* d_out, int out_size)
{
    const float* x    = (const float*)d_in[0];
    const int*   ei   = (const int*)  d_in[1];
    const int*   src  = ei;
    const int*   dst  = ei + EE;
    const int*   mask = (const int*)  d_in[2];
    const float* Wg   = (const float*)d_in[3];
    const float* bg   = (const float*)d_in[4];
    const float* bn_g = (const float*)d_in[5];
    const float* bn_b = (const float*)d_in[6];
    const float* Wl   = (const float*)d_in[7];
    float* z = (float*)d_out;

    float *XW,*XWb,*XWc,*Ya,*Yb,*Yc,*S,*X2,*P,*T,*X3,*A,*ATT,*VC;
    float *ds1,*ds2,*sf1,*sf2,*stats,*part,*nrmP1,*nrmP2;
    int *cnt,*cnt2,*rowptr,*cursor,*eids,*srcP,*bsum,*boff;
    cudaGetSymbolAddress((void**)&XW,  g_XW);
    cudaGetSymbolAddress((void**)&XWb, g_XWb);
    cudaGetSymbolAddress((void**)&XWc, g_XWc);
    cudaGetSymbolAddress((void**)&Ya,  g_Ya);
    cudaGetSymbolAddress((void**)&Yb,  g_Yb);
    cudaGetSymbolAddress((void**)&Yc,  g_Yc);
    cudaGetSymbolAddress((void**)&S,   g_S);
    cudaGetSymbolAddress((void**)&X2,  g_X2);
    cudaGetSymbolAddress((void**)&P,   g_P);
    cudaGetSymbolAddress((void**)&T,   g_T);
    cudaGetSymbolAddress((void**)&X3,  g_X3);
    cudaGetSymbolAddress((void**)&A,   g_A);
    cudaGetSymbolAddress((void**)&ATT, g_ATT);
    cudaGetSymbolAddress((void**)&VC,  g_VC);
    cudaGetSymbolAddress((void**)&cnt, g_cnt);
    cudaGetSymbolAddress((void**)&cnt2,g_cnt2);
    cudaGetSymbolAddress((void**)&rowptr, g_rowptr);
    cudaGetSymbolAddress((void**)&cursor, g_cursor);
    cudaGetSymbolAddress((void**)&eids,   g_eids);
    cudaGetSymbolAddress((void**)&srcP,   g_srcP);
    cudaGetSymbolAddress((void**)&nrmP1,  g_nrmP1);
    cudaGetSymbolAddress((void**)&nrmP2,  g_nrmP2);
    cudaGetSymbolAddress((void**)&bsum,   g_bsum);
    cudaGetSymbolAddress((void**)&boff,   g_boff);
    cudaGetSymbolAddress((void**)&ds1, g_dis1);
    cudaGetSymbolAddress((void**)&ds2, g_dis2);
    cudaGetSymbolAddress((void**)&sf1, g_self1);
    cudaGetSymbolAddress((void**)&sf2, g_self2);
    cudaGetSymbolAddress((void**)&stats, g_stats);
    cudaGetSymbolAddress((void**)&part,  g_part);

    // ---- per-launch preprocessing (graph replays everything) ----
    k_init <<<1024,256>>>(cnt, cnt2, VC);
    k_count<<<(EE+255)/256,256>>>(dst, mask, cnt, cnt2);
    k_scan1<<<NB,1024>>>(cnt, rowptr, bsum);
    k_scan2<<<1,32>>>(bsum, boff, rowptr);
    k_scan3<<<(NN+255)/256,256>>>(boff, rowptr, cursor);
    k_fill <<<(EE+255)/256,256>>>(dst, cursor, eids);
    k_sortbuckets<<<(NN+255)/256,256>>>(rowptr, eids);
    k_dis  <<<(NN+255)/256,256>>>(cnt, cnt2, ds1, ds2, sf1, sf2);
    k_permute<<<(EE+255)/256,256>>>(eids, src, dst, mask, ds1, ds2, srcP, nrmP1, nrmP2);

    // enc 1 (w = ones), enc 2 (w = mask); conv_lif state VC carries over
    run_enc(x, Wg, bg, bn_g, bn_b, nrmP1, srcP, sf1, rowptr,
            stats,        part, Wl, z,
            XW, XWb, XWc, Ya, Yb, Yc, S, X2, P, T, X3, A, ATT, VC);
    run_enc(x, Wg, bg, bn_g, bn_b, nrmP2, srcP, sf2, rowptr,
            stats+9*128,  part, Wl, z+NN,
            XW, XWb, XWc, Ya, Yb, Yc, S, X2, P, T, X3, A, ATT, VC);
}